// round 11
// baseline (speedup 1.0000x reference)
#include <cuda_runtime.h>
#include <cstdint>
#include <cstddef>

#define DIM_TOTAL 1920
#define W_TOTAL   344064

__device__ float g_wt[W_TOTAL];   // preprocessed weights: transposed, tf32, scaled, k-permuted

__device__ __forceinline__ uint32_t f2tf32(float f) {
    uint32_t u;
    asm("cvt.rna.tf32.f32 %0, %1;" : "=r"(u) : "f"(f));
    return u;
}

__device__ __forceinline__ void cp16(float* dst, const float* src) {
    uint32_t d = (uint32_t)__cvta_generic_to_shared(dst);
    asm volatile("cp.async.cg.shared.global [%0], [%1], 16;" :: "r"(d), "l"(src));
}

// Wt[seg][v][k'] = rna_tf32( W[k][v] * scale ), k' = k with within-8 permutation
// [0,4,1,5,2,6,3,7] so mma B frag pair (q, q+4) is one contiguous float2.
__global__ void prep_weights(const float* __restrict__ w) {
    int i = blockIdx.x * 256 + threadIdx.x;      // source index into w
    int base, mul; float scale;
    if (i < 262144)      { base = 0;      mul = 512; scale = 0.044194173824159216f; }
    else if (i < 327680) { base = 262144; mul = 256; scale = 0.0625f; }
    else                 { base = 327680; mul = 128; scale = 0.08838834764831843f; }
    int local = i - base;
    int u = local / mul, v = local - u * mul;    // W[u][v], u = input channel
    int newk = ((u & 3) << 1) | ((u >> 2) & 1);  // position within 8-block
    g_wt[base + v * mul + (u & ~7) + newk] = __uint_as_float(f2tf32(w[i] * scale));
}

// Segmented linear as tensor-core GEMM, cp.async 3-stage pipeline.
// Component-expanded rows r = n*D + i; A'[r][u] = x[n, XOFF + u*D + i].
// A fragments: raw fp32 (HMMA truncates to tf32). B: preprocessed Wt,
// loaded K-contiguous, fragments via single LDS.64 (no CVT in mainloop).
template<int D, int BM, int BN, int BK, int WM, int WN, int XOFF, int MUL>
__global__ void __launch_bounds__((BM/WM)*(BN/WN)*32, 1)
seg_linear_tc(const float* __restrict__ x, float* __restrict__ out, int woff)
{
    constexpr int THREADS = (BM/WM)*(BN/WN)*32;
    constexpr int NPB   = BM/D;          // tokens per block
    constexpr int ATOK  = BK*D + 4;      // A smem floats per token per stage
    constexpr int BSTR  = BK + 8;        // B row stride (==8 mod 32: LDS.64 conflict-free)
    constexpr int A_F   = NPB*ATOK;
    constexpr int B_F   = BN*BSTR;
    constexpr int STAGE_F = A_F + B_F;
    constexpr int CPN   = BK*D/4;        // A 16B chunks per token per tile
    constexpr int A_CH  = NPB*CPN;
    constexpr int B_CH  = BN*BK/4;
    constexpr int KT    = MUL/BK;
    constexpr int MT    = WM/16, NT = WN/8;
    constexpr int WARPS_N = BN/WN;

    static_assert(BM % D == 0, "whole tokens per block");
    static_assert(A_CH % THREADS == 0 && B_CH % THREADS == 0, "copy divides");
    static_assert((BM*BN/4) % THREADS == 0, "epilogue divides");
    static_assert(KT >= 2, "pipeline needs >=2 tiles");

    extern __shared__ float sm[];

    const int tid  = threadIdx.x;
    const int warp = tid >> 5, lane = tid & 31;
    const int g = lane >> 2, q = lane & 3;
    const int wy = warp / WARPS_N, wx = warp % WARPS_N;
    const int n0g = blockIdx.x * NPB;
    const int v0  = blockIdx.y * BN;
    const float* wt = g_wt + woff;

    auto load_stage = [&](int kt, float* st) {
        float* As = st;
        float* Bs = st + A_F;
        #pragma unroll
        for (int it = 0; it < A_CH/THREADS; ++it) {
            int idx = tid + it*THREADS;
            int nl = idx / CPN, c4 = idx - nl*CPN;
            cp16(As + nl*ATOK + c4*4,
                 x + (size_t)(n0g + nl)*DIM_TOTAL + XOFF + kt*(BK*D) + c4*4);
        }
        #pragma unroll
        for (int it = 0; it < B_CH/THREADS; ++it) {
            int idx = tid + it*THREADS;
            int v = idx / (BK/4), c4 = idx - v*(BK/4);
            cp16(Bs + v*BSTR + c4*4,
                 wt + (size_t)(v0 + v)*MUL + kt*BK + c4*4);
        }
    };

    float acc[MT][NT][4];
    #pragma unroll
    for (int mt = 0; mt < MT; ++mt)
        #pragma unroll
        for (int nt = 0; nt < NT; ++nt)
            #pragma unroll
            for (int e = 0; e < 4; ++e)
                acc[mt][nt][e] = 0.0f;

    // per-row A offsets (irrep de-interleave hoisted out of the k loop)
    int aOff0[MT], aOff1[MT];
    #pragma unroll
    for (int mt = 0; mt < MT; ++mt) {
        int r0 = wy*WM + mt*16 + g;
        int r1 = r0 + 8;
        aOff0[mt] = (r0/D)*ATOK + (r0 - (r0/D)*D) + q*D;
        aOff1[mt] = (r1/D)*ATOK + (r1 - (r1/D)*D) + q*D;
    }
    int bOff[NT];
    #pragma unroll
    for (int nt = 0; nt < NT; ++nt)
        bOff[nt] = (wx*WN + nt*8 + g)*BSTR + 2*q;

    load_stage(0, sm);
    asm volatile("cp.async.commit_group;" ::: "memory");
    load_stage(1, sm + STAGE_F);
    asm volatile("cp.async.commit_group;" ::: "memory");

    int sidx = 0;
    for (int kt = 0; kt < KT; ++kt) {
        asm volatile("cp.async.wait_group 1;" ::: "memory");
        __syncthreads();
        if (kt + 2 < KT) {
            int ns = sidx + 2; if (ns >= 3) ns -= 3;
            load_stage(kt + 2, sm + ns*STAGE_F);
        }
        asm volatile("cp.async.commit_group;" ::: "memory");

        const float* As = sm + sidx*STAGE_F;
        const float* Bs = As + A_F;
        #pragma unroll
        for (int kk = 0; kk < BK/8; ++kk) {
            uint32_t a[MT][4];
            #pragma unroll
            for (int mt = 0; mt < MT; ++mt) {   // raw fp32: HW truncates to tf32
                a[mt][0] = __float_as_uint(As[aOff0[mt] + (kk*8)*D]);
                a[mt][1] = __float_as_uint(As[aOff1[mt] + (kk*8)*D]);
                a[mt][2] = __float_as_uint(As[aOff0[mt] + (kk*8 + 4)*D]);
                a[mt][3] = __float_as_uint(As[aOff1[mt] + (kk*8 + 4)*D]);
            }
            uint32_t b[NT][2];
            #pragma unroll
            for (int nt = 0; nt < NT; ++nt) {   // one LDS.64: pre-permuted (q, q+4)
                float2 bv = *reinterpret_cast<const float2*>(&Bs[bOff[nt] + kk*8]);
                b[nt][0] = __float_as_uint(bv.x);
                b[nt][1] = __float_as_uint(bv.y);
            }
            #pragma unroll
            for (int mt = 0; mt < MT; ++mt)
                #pragma unroll
                for (int nt = 0; nt < NT; ++nt)
                    asm volatile(
                        "mma.sync.aligned.m16n8k8.row.col.f32.tf32.tf32.f32 "
                        "{%0,%1,%2,%3}, {%4,%5,%6,%7}, {%8,%9}, {%0,%1,%2,%3};"
                        : "+f"(acc[mt][nt][0]), "+f"(acc[mt][nt][1]),
                          "+f"(acc[mt][nt][2]), "+f"(acc[mt][nt][3])
                        : "r"(a[mt][0]), "r"(a[mt][1]), "r"(a[mt][2]), "r"(a[mt][3]),
                          "r"(b[nt][0]), "r"(b[nt][1]));
        }
        ++sidx; if (sidx >= 3) sidx = 0;
    }

    // ---- epilogue: stage C in smem (stages dead), contiguous float4 stores ----
    __syncthreads();
    float (*C)[BN] = reinterpret_cast<float (*)[BN]>(sm);
    #pragma unroll
    for (int mt = 0; mt < MT; ++mt)
        #pragma unroll
        for (int nt = 0; nt < NT; ++nt) {
            int r   = wy*WM + mt*16 + g;
            int col = wx*WN + nt*8 + 2*q;
            C[r    ][col    ] = acc[mt][nt][0];
            C[r    ][col + 1] = acc[mt][nt][1];
            C[r + 8][col    ] = acc[mt][nt][2];
            C[r + 8][col + 1] = acc[mt][nt][3];
        }
    __syncthreads();

    constexpr int TOT4 = BM*BN/4;
    #pragma unroll
    for (int it = 0; it < TOT4/THREADS; ++it) {
        int f    = tid + it*THREADS;
        int base = f*4;
        int nl   = base / (BN*D);
        int j    = base - nl*(BN*D);
        float4 vv;
        vv.x = C[nl*D + (j+0)%D][(j+0)/D];
        vv.y = C[nl*D + (j+1)%D][(j+1)/D];
        vv.z = C[nl*D + (j+2)%D][(j+2)/D];
        vv.w = C[nl*D + (j+3)%D][(j+3)/D];
        *reinterpret_cast<float4*>(
            out + (size_t)(n0g + nl)*DIM_TOTAL + XOFF + v0*D + j) = vv;
    }
}

extern "C" void kernel_launch(void* const* d_in, const int* in_sizes, int n_in,
                              void* d_out, int out_size)
{
    const float* x   = (const float*)d_in[0];
    const float* w   = (const float*)d_in[1];
    float*       out = (float*)d_out;
    (void)in_sizes; (void)n_in; (void)out_size;

    // Stage 0: preprocess weights (transpose + tf32 + scale fold + k-perm).
    prep_weights<<<W_TOTAL/256, 256>>>(w);

    // seg0: D=1, MUL=512. Tile 128x256x32, 8 warps of 64x64.
    {
        auto kfn = seg_linear_tc<1,128,256,32,64,64,0,512>;
        constexpr int STAGE_B = (128*(32+4) + 256*(32+8))*4;   // 59392
        constexpr int SMEM = (3*STAGE_B > 128*256*4) ? 3*STAGE_B : 128*256*4; // 178176
        cudaFuncSetAttribute(kfn, cudaFuncAttributeMaxDynamicSharedMemorySize, SMEM);
        dim3 grid(16384/128, 512/256);
        kfn<<<grid, 256, SMEM>>>(x, out, 0);
    }
    // seg1: D=3, MUL=256. Tile 96x256x32, 8 warps of 48x64.
    {
        auto kfn = seg_linear_tc<3,96,256,32,48,64,512,256>;
        constexpr int STAGE_B = (32*(96+4) + 256*(32+8))*4;    // 53760
        constexpr int SMEM = (3*STAGE_B > 96*256*4) ? 3*STAGE_B : 96*256*4;   // 161280
        cudaFuncSetAttribute(kfn, cudaFuncAttributeMaxDynamicSharedMemorySize, SMEM);
        dim3 grid(49152/96, 256/256);
        kfn<<<grid, 256, SMEM>>>(x, out, 262144);
    }
    // seg2: D=5, MUL=128. Tile 160x128x16, 4 warps of 80x64.
    {
        auto kfn = seg_linear_tc<5,160,128,16,80,64,1280,128>;
        constexpr int STAGE_B = (32*(16*5+4) + 128*(16+8))*4;  // 23040
        constexpr int SMEM = (3*STAGE_B > 160*128*4) ? 3*STAGE_B : 160*128*4; // 81920
        cudaFuncSetAttribute(kfn, cudaFuncAttributeMaxDynamicSharedMemorySize, SMEM);
        dim3 grid(81920/160, 128/128);
        kfn<<<grid, 128, SMEM>>>(x, out, 327680);
    }
}

// round 16
// speedup vs baseline: 1.6820x; 1.6820x over previous
#include <cuda_runtime.h>
#include <cstdint>
#include <cstddef>

#define DIM_TOTAL 1920
#define W_TOTAL   344064

// Preprocessed weights: SAME [k][v] layout as source, values tf32-rounded
// with 1/sqrt(mul) folded in. Mainloop then needs no CVT and no epilogue scale.
__device__ float g_wt[W_TOTAL];

__device__ __forceinline__ uint32_t f2tf32(float f) {
    uint32_t u;
    asm("cvt.rna.tf32.f32 %0, %1;" : "=r"(u) : "f"(f));
    return u;
}

__global__ void prep_weights(const float* __restrict__ w) {
    int i = blockIdx.x * 256 + threadIdx.x;
    float scale;
    if (i < 262144)      scale = 0.044194173824159216f;  // 1/sqrt(512)
    else if (i < 327680) scale = 0.0625f;                // 1/sqrt(256)
    else                 scale = 0.08838834764831843f;   // 1/sqrt(128)
    g_wt[i] = __uint_as_float(f2tf32(w[i] * scale));
}

__device__ __forceinline__ void cp16(float* dst, const float* src) {
    uint32_t d = (uint32_t)__cvta_generic_to_shared(dst);
    asm volatile("cp.async.cg.shared.global [%0], [%1], 16;" :: "r"(d), "l"(src));
}

// Segmented linear as tensor-core GEMM, cp.async 3-stage pipeline.
// Geometry, smem layout, and B memory path identical to the 153.7us round-7
// kernel; only difference: B values come pre-converted/pre-scaled from g_wt,
// so the mainloop has zero CVTs and the epilogue no scale multiply.
template<int D, int BM, int BN, int BK, int WM, int WN, int XOFF, int MUL>
__global__ void __launch_bounds__((BM/WM)*(BN/WN)*32, 2)
seg_linear_tc(const float* __restrict__ x, float* __restrict__ out, int woff)
{
    constexpr int THREADS = (BM/WM)*(BN/WN)*32;
    constexpr int NPB   = BM/D;          // tokens per block
    constexpr int ATOK  = BK*D + 4;      // A smem floats per token per stage
    constexpr int BSTR  = BN + 8;        // B row stride (conflict-free frag loads)
    constexpr int A_F   = NPB*ATOK;
    constexpr int B_F   = BK*BSTR;
    constexpr int STAGE_F = A_F + B_F;
    constexpr int CPN   = BK*D/4;        // A 16B chunks per token per tile
    constexpr int A_CH  = NPB*CPN;
    constexpr int B_CH  = BK*BN/4;
    constexpr int KT    = MUL/BK;
    constexpr int MT    = WM/16, NT = WN/8;
    constexpr int WARPS_N = BN/WN;

    static_assert(BM % D == 0, "whole tokens per block");
    static_assert(A_CH % THREADS == 0 && B_CH % THREADS == 0, "copy divides");
    static_assert((BM*BN/4) % THREADS == 0, "epilogue divides");
    static_assert(KT >= 2, "pipeline needs >=2 tiles");

    extern __shared__ float sm[];

    const int tid  = threadIdx.x;
    const int warp = tid >> 5, lane = tid & 31;
    const int g = lane >> 2, q = lane & 3;
    const int wy = warp / WARPS_N, wx = warp % WARPS_N;
    const int n0g = blockIdx.x * NPB;
    const int v0  = blockIdx.y * BN;
    const float* wt = g_wt + woff;

    auto load_stage = [&](int kt, float* st) {
        float* As = st;
        float* Bs = st + A_F;
        #pragma unroll
        for (int it = 0; it < A_CH/THREADS; ++it) {
            int idx = tid + it*THREADS;
            int nl = idx / CPN, c4 = idx - nl*CPN;
            cp16(As + nl*ATOK + c4*4,
                 x + (size_t)(n0g + nl)*DIM_TOTAL + XOFF + kt*(BK*D) + c4*4);
        }
        #pragma unroll
        for (int it = 0; it < B_CH/THREADS; ++it) {
            int idx = tid + it*THREADS;
            int r = idx / (BN/4), c4 = idx - r*(BN/4);
            cp16(Bs + r*BSTR + c4*4,
                 wt + (size_t)(kt*BK + r)*MUL + v0 + c4*4);
        }
    };

    float acc[MT][NT][4];
    #pragma unroll
    for (int mt = 0; mt < MT; ++mt)
        #pragma unroll
        for (int nt = 0; nt < NT; ++nt)
            #pragma unroll
            for (int e = 0; e < 4; ++e)
                acc[mt][nt][e] = 0.0f;

    // per-row A offsets (irrep de-interleave hoisted out of the k loop)
    int aOff0[MT], aOff1[MT];
    #pragma unroll
    for (int mt = 0; mt < MT; ++mt) {
        int r0 = wy*WM + mt*16 + g;
        int r1 = r0 + 8;
        aOff0[mt] = (r0/D)*ATOK + (r0 - (r0/D)*D) + q*D;
        aOff1[mt] = (r1/D)*ATOK + (r1 - (r1/D)*D) + q*D;
    }
    int bCol[NT];
    #pragma unroll
    for (int nt = 0; nt < NT; ++nt)
        bCol[nt] = wx*WN + nt*8 + g;

    load_stage(0, sm);
    asm volatile("cp.async.commit_group;" ::: "memory");
    load_stage(1, sm + STAGE_F);
    asm volatile("cp.async.commit_group;" ::: "memory");

    int sidx = 0;
    for (int kt = 0; kt < KT; ++kt) {
        asm volatile("cp.async.wait_group 1;" ::: "memory");
        __syncthreads();
        if (kt + 2 < KT) {
            int ns = sidx + 2; if (ns >= 3) ns -= 3;
            load_stage(kt + 2, sm + ns*STAGE_F);
        }
        asm volatile("cp.async.commit_group;" ::: "memory");

        const float* As = sm + sidx*STAGE_F;
        const float* Bs = As + A_F;
        #pragma unroll
        for (int kk = 0; kk < BK/8; ++kk) {
            uint32_t a[MT][4];
            #pragma unroll
            for (int mt = 0; mt < MT; ++mt) {   // raw fp32: HMMA truncates to tf32
                a[mt][0] = __float_as_uint(As[aOff0[mt] + (kk*8)*D]);
                a[mt][1] = __float_as_uint(As[aOff1[mt] + (kk*8)*D]);
                a[mt][2] = __float_as_uint(As[aOff0[mt] + (kk*8 + 4)*D]);
                a[mt][3] = __float_as_uint(As[aOff1[mt] + (kk*8 + 4)*D]);
            }
            uint32_t b[NT][2];
            #pragma unroll
            for (int nt = 0; nt < NT; ++nt) {   // pre-converted: raw LDS, no CVT
                b[nt][0] = __float_as_uint(Bs[(kk*8 + q    )*BSTR + bCol[nt]]);
                b[nt][1] = __float_as_uint(Bs[(kk*8 + q + 4)*BSTR + bCol[nt]]);
            }
            #pragma unroll
            for (int mt = 0; mt < MT; ++mt)
                #pragma unroll
                for (int nt = 0; nt < NT; ++nt)
                    asm volatile(
                        "mma.sync.aligned.m16n8k8.row.col.f32.tf32.tf32.f32 "
                        "{%0,%1,%2,%3}, {%4,%5,%6,%7}, {%8,%9}, {%0,%1,%2,%3};"
                        : "+f"(acc[mt][nt][0]), "+f"(acc[mt][nt][1]),
                          "+f"(acc[mt][nt][2]), "+f"(acc[mt][nt][3])
                        : "r"(a[mt][0]), "r"(a[mt][1]), "r"(a[mt][2]), "r"(a[mt][3]),
                          "r"(b[nt][0]), "r"(b[nt][1]));
        }
        ++sidx; if (sidx >= 3) sidx = 0;
    }

    // ---- epilogue: stage C in smem (stages dead), contiguous float4 stores ----
    __syncthreads();
    float (*C)[BN] = reinterpret_cast<float (*)[BN]>(sm);
    #pragma unroll
    for (int mt = 0; mt < MT; ++mt)
        #pragma unroll
        for (int nt = 0; nt < NT; ++nt) {
            int r   = wy*WM + mt*16 + g;
            int col = wx*WN + nt*8 + 2*q;
            C[r    ][col    ] = acc[mt][nt][0];
            C[r    ][col + 1] = acc[mt][nt][1];
            C[r + 8][col    ] = acc[mt][nt][2];
            C[r + 8][col + 1] = acc[mt][nt][3];
        }
    __syncthreads();

    constexpr int TOT4 = BM*BN/4;
    #pragma unroll
    for (int it = 0; it < TOT4/THREADS; ++it) {
        int f    = tid + it*THREADS;
        int base = f*4;
        int nl   = base / (BN*D);
        int j    = base - nl*(BN*D);
        float4 vv;                                // scale pre-folded into Wt
        vv.x = C[nl*D + (j+0)%D][(j+0)/D];
        vv.y = C[nl*D + (j+1)%D][(j+1)/D];
        vv.z = C[nl*D + (j+2)%D][(j+2)/D];
        vv.w = C[nl*D + (j+3)%D][(j+3)/D];
        *reinterpret_cast<float4*>(
            out + (size_t)(n0g + nl)*DIM_TOTAL + XOFF + v0*D + j) = vv;
    }
}

extern "C" void kernel_launch(void* const* d_in, const int* in_sizes, int n_in,
                              void* d_out, int out_size)
{
    const float* x   = (const float*)d_in[0];
    const float* w   = (const float*)d_in[1];
    float*       out = (float*)d_out;
    (void)in_sizes; (void)n_in; (void)out_size;

    // Stage 0: in-layout weight preprocess (tf32 round + scale fold).
    prep_weights<<<W_TOTAL/256, 256>>>(w);

    // seg0: D=1, MUL=512. Tile 128x128x32, 4 warps of 64x64 (round-7 geometry).
    {
        auto kfn = seg_linear_tc<1,128,128,32,64,64,0,512>;
        constexpr int STAGE_B = (128*(32+4) + 32*(128+8))*4;   // 35840
        constexpr int SMEM = (3*STAGE_B > 128*128*4) ? 3*STAGE_B : 128*128*4; // 107520
        cudaFuncSetAttribute(kfn, cudaFuncAttributeMaxDynamicSharedMemorySize, SMEM);
        dim3 grid(16384/128, 512/128);
        kfn<<<grid, 128, SMEM>>>(x, out, 0);
    }
    // seg1: D=3, MUL=256. Tile 96x128x32, 4 warps of 48x64.
    {
        auto kfn = seg_linear_tc<3,96,128,32,48,64,512,256>;
        constexpr int STAGE_B = (32*(96+4) + 32*(128+8))*4;    // 30208
        constexpr int SMEM = (3*STAGE_B > 96*128*4) ? 3*STAGE_B : 96*128*4;   // 90624
        cudaFuncSetAttribute(kfn, cudaFuncAttributeMaxDynamicSharedMemorySize, SMEM);
        dim3 grid(49152/96, 256/128);
        kfn<<<grid, 128, SMEM>>>(x, out, 262144);
    }
    // seg2: D=5, MUL=128. Tile 160x128x16, 4 warps of 80x64.
    {
        auto kfn = seg_linear_tc<5,160,128,16,80,64,1280,128>;
        constexpr int STAGE_B = (32*(16*5+4) + 16*(128+8))*4;  // 19456
        constexpr int SMEM = (3*STAGE_B > 160*128*4) ? 3*STAGE_B : 160*128*4; // 81920
        cudaFuncSetAttribute(kfn, cudaFuncAttributeMaxDynamicSharedMemorySize, SMEM);
        dim3 grid(81920/160, 128/128);
        kfn<<<grid, 128, SMEM>>>(x, out, 327680);
    }
}

// round 17
// speedup vs baseline: 1.6827x; 1.0004x over previous
#include <cuda_runtime.h>
#include <cstdint>
#include <cstddef>

#define DIM_TOTAL 1920
#define W_TOTAL   344064

// Preprocessed weights: SAME [k][v] layout as source, values tf32-rounded
// with 1/sqrt(mul) folded in. Mainloop then needs no CVT and no epilogue scale.
__device__ float g_wt[W_TOTAL];

__device__ __forceinline__ uint32_t f2tf32(float f) {
    uint32_t u;
    asm("cvt.rna.tf32.f32 %0, %1;" : "=r"(u) : "f"(f));
    return u;
}

__global__ void prep_weights(const float* __restrict__ w) {
    int i = blockIdx.x * 256 + threadIdx.x;
    float scale;
    if (i < 262144)      scale = 0.044194173824159216f;  // 1/sqrt(512)
    else if (i < 327680) scale = 0.0625f;                // 1/sqrt(256)
    else                 scale = 0.08838834764831843f;   // 1/sqrt(128)
    g_wt[i] = __uint_as_float(f2tf32(w[i] * scale));
}

__device__ __forceinline__ void cp16(float* dst, const float* src) {
    uint32_t d = (uint32_t)__cvta_generic_to_shared(dst);
    asm volatile("cp.async.cg.shared.global [%0], [%1], 16;" :: "r"(d), "l"(src));
}

// Segmented linear as tensor-core GEMM, cp.async 3-stage pipeline.
// DB=true adds explicit fragment double-buffering across the kk loop:
// the LDS for step kk+1 issue before the HMMAs of step kk, so shared-memory
// latency drains behind tensor work (the round-9 binder at 2 warps/SMSP).
template<int D, int BM, int BN, int BK, int WM, int WN, int XOFF, int MUL, bool DB>
__global__ void __launch_bounds__((BM/WM)*(BN/WN)*32, 2)
seg_linear_tc(const float* __restrict__ x, float* __restrict__ out, int woff)
{
    constexpr int THREADS = (BM/WM)*(BN/WN)*32;
    constexpr int NPB   = BM/D;          // tokens per block
    constexpr int ATOK  = BK*D + 4;      // A smem floats per token per stage
    constexpr int BSTR  = BN + 8;        // B row stride (conflict-free frag loads)
    constexpr int A_F   = NPB*ATOK;
    constexpr int B_F   = BK*BSTR;
    constexpr int STAGE_F = A_F + B_F;
    constexpr int CPN   = BK*D/4;        // A 16B chunks per token per tile
    constexpr int A_CH  = NPB*CPN;
    constexpr int B_CH  = BK*BN/4;
    constexpr int KT    = MUL/BK;
    constexpr int MT    = WM/16, NT = WN/8;
    constexpr int KK    = BK/8;
    constexpr int WARPS_N = BN/WN;

    static_assert(BM % D == 0, "whole tokens per block");
    static_assert(A_CH % THREADS == 0 && B_CH % THREADS == 0, "copy divides");
    static_assert((BM*BN/4) % THREADS == 0, "epilogue divides");
    static_assert(KT >= 2, "pipeline needs >=2 tiles");

    extern __shared__ float sm[];

    const int tid  = threadIdx.x;
    const int warp = tid >> 5, lane = tid & 31;
    const int g = lane >> 2, q = lane & 3;
    const int wy = warp / WARPS_N, wx = warp % WARPS_N;
    const int n0g = blockIdx.x * NPB;
    const int v0  = blockIdx.y * BN;
    const float* wt = g_wt + woff;

    auto load_stage = [&](int kt, float* st) {
        float* As = st;
        float* Bs = st + A_F;
        #pragma unroll
        for (int it = 0; it < A_CH/THREADS; ++it) {
            int idx = tid + it*THREADS;
            int nl = idx / CPN, c4 = idx - nl*CPN;
            cp16(As + nl*ATOK + c4*4,
                 x + (size_t)(n0g + nl)*DIM_TOTAL + XOFF + kt*(BK*D) + c4*4);
        }
        #pragma unroll
        for (int it = 0; it < B_CH/THREADS; ++it) {
            int idx = tid + it*THREADS;
            int r = idx / (BN/4), c4 = idx - r*(BN/4);
            cp16(Bs + r*BSTR + c4*4,
                 wt + (size_t)(kt*BK + r)*MUL + v0 + c4*4);
        }
    };

    float acc[MT][NT][4];
    #pragma unroll
    for (int mt = 0; mt < MT; ++mt)
        #pragma unroll
        for (int nt = 0; nt < NT; ++nt)
            #pragma unroll
            for (int e = 0; e < 4; ++e)
                acc[mt][nt][e] = 0.0f;

    // per-row A offsets (irrep de-interleave hoisted out of the k loop)
    int aOff0[MT], aOff1[MT];
    #pragma unroll
    for (int mt = 0; mt < MT; ++mt) {
        int r0 = wy*WM + mt*16 + g;
        int r1 = r0 + 8;
        aOff0[mt] = (r0/D)*ATOK + (r0 - (r0/D)*D) + q*D;
        aOff1[mt] = (r1/D)*ATOK + (r1 - (r1/D)*D) + q*D;
    }
    int bCol[NT];
    #pragma unroll
    for (int nt = 0; nt < NT; ++nt)
        bCol[nt] = wx*WN + nt*8 + g;

    load_stage(0, sm);
    asm volatile("cp.async.commit_group;" ::: "memory");
    load_stage(1, sm + STAGE_F);
    asm volatile("cp.async.commit_group;" ::: "memory");

    uint32_t aF[DB ? 2 : 1][MT][4];
    uint32_t bF[DB ? 2 : 1][NT][2];

    auto ld_frags = [&](const float* As, const float* Bs, int kk,
                        uint32_t (*a)[4], uint32_t (*b)[2]) {
        #pragma unroll
        for (int mt = 0; mt < MT; ++mt) {   // raw fp32: HMMA truncates to tf32
            a[mt][0] = __float_as_uint(As[aOff0[mt] + (kk*8)*D]);
            a[mt][1] = __float_as_uint(As[aOff1[mt] + (kk*8)*D]);
            a[mt][2] = __float_as_uint(As[aOff0[mt] + (kk*8 + 4)*D]);
            a[mt][3] = __float_as_uint(As[aOff1[mt] + (kk*8 + 4)*D]);
        }
        #pragma unroll
        for (int nt = 0; nt < NT; ++nt) {   // pre-converted in g_wt: no CVT
            b[nt][0] = __float_as_uint(Bs[(kk*8 + q    )*BSTR + bCol[nt]]);
            b[nt][1] = __float_as_uint(Bs[(kk*8 + q + 4)*BSTR + bCol[nt]]);
        }
    };
    auto mma_all = [&](uint32_t (*a)[4], uint32_t (*b)[2]) {
        #pragma unroll
        for (int mt = 0; mt < MT; ++mt)
            #pragma unroll
            for (int nt = 0; nt < NT; ++nt)
                asm volatile(
                    "mma.sync.aligned.m16n8k8.row.col.f32.tf32.tf32.f32 "
                    "{%0,%1,%2,%3}, {%4,%5,%6,%7}, {%8,%9}, {%0,%1,%2,%3};"
                    : "+f"(acc[mt][nt][0]), "+f"(acc[mt][nt][1]),
                      "+f"(acc[mt][nt][2]), "+f"(acc[mt][nt][3])
                    : "r"(a[mt][0]), "r"(a[mt][1]), "r"(a[mt][2]), "r"(a[mt][3]),
                      "r"(b[nt][0]), "r"(b[nt][1]));
    };

    int sidx = 0;
    for (int kt = 0; kt < KT; ++kt) {
        asm volatile("cp.async.wait_group 1;" ::: "memory");
        __syncthreads();
        if (kt + 2 < KT) {
            int ns = sidx + 2; if (ns >= 3) ns -= 3;
            load_stage(kt + 2, sm + ns*STAGE_F);
        }
        asm volatile("cp.async.commit_group;" ::: "memory");

        const float* As = sm + sidx*STAGE_F;
        const float* Bs = As + A_F;
        if (DB) {
            ld_frags(As, Bs, 0, aF[0], bF[0]);
            #pragma unroll
            for (int kk = 0; kk < KK; ++kk) {
                if (kk + 1 < KK)
                    ld_frags(As, Bs, kk + 1, aF[(kk+1)&1], bF[(kk+1)&1]);
                mma_all(aF[kk&1], bF[kk&1]);
            }
        } else {
            #pragma unroll
            for (int kk = 0; kk < KK; ++kk) {
                ld_frags(As, Bs, kk, aF[0], bF[0]);
                mma_all(aF[0], bF[0]);
            }
        }
        ++sidx; if (sidx >= 3) sidx = 0;
    }

    // ---- epilogue: stage C in smem (stages dead), contiguous float4 stores ----
    __syncthreads();
    float (*C)[BN] = reinterpret_cast<float (*)[BN]>(sm);
    #pragma unroll
    for (int mt = 0; mt < MT; ++mt)
        #pragma unroll
        for (int nt = 0; nt < NT; ++nt) {
            int r   = wy*WM + mt*16 + g;
            int col = wx*WN + nt*8 + 2*q;
            C[r    ][col    ] = acc[mt][nt][0];
            C[r    ][col + 1] = acc[mt][nt][1];
            C[r + 8][col    ] = acc[mt][nt][2];
            C[r + 8][col + 1] = acc[mt][nt][3];
        }
    __syncthreads();

    constexpr int TOT4 = BM*BN/4;
    #pragma unroll
    for (int it = 0; it < TOT4/THREADS; ++it) {
        int f    = tid + it*THREADS;
        int base = f*4;
        int nl   = base / (BN*D);
        int j    = base - nl*(BN*D);
        float4 vv;                                // scale pre-folded into Wt
        vv.x = C[nl*D + (j+0)%D][(j+0)/D];
        vv.y = C[nl*D + (j+1)%D][(j+1)/D];
        vv.z = C[nl*D + (j+2)%D][(j+2)/D];
        vv.w = C[nl*D + (j+3)%D][(j+3)/D];
        *reinterpret_cast<float4*>(
            out + (size_t)(n0g + nl)*DIM_TOTAL + XOFF + v0*D + j) = vv;
    }
}

extern "C" void kernel_launch(void* const* d_in, const int* in_sizes, int n_in,
                              void* d_out, int out_size)
{
    const float* x   = (const float*)d_in[0];
    const float* w   = (const float*)d_in[1];
    float*       out = (float*)d_out;
    (void)in_sizes; (void)n_in; (void)out_size;

    // Stage 0: in-layout weight preprocess (tf32 round + scale fold).
    prep_weights<<<W_TOTAL/256, 256>>>(w);

    // seg0: D=1, MUL=512. Tile 128x128x32, 4 warps of 64x64, frag double-buffer.
    {
        auto kfn = seg_linear_tc<1,128,128,32,64,64,0,512,true>;
        constexpr int STAGE_B = (128*(32+4) + 32*(128+8))*4;   // 35840
        constexpr int SMEM = (3*STAGE_B > 128*128*4) ? 3*STAGE_B : 128*128*4; // 107520
        cudaFuncSetAttribute(kfn, cudaFuncAttributeMaxDynamicSharedMemorySize, SMEM);
        dim3 grid(16384/128, 512/128);
        kfn<<<grid, 128, SMEM>>>(x, out, 0);
    }
    // seg1: D=3, MUL=256. Tile 96x128x32, 4 warps of 48x64, frag double-buffer.
    {
        auto kfn = seg_linear_tc<3,96,128,32,48,64,512,256,true>;
        constexpr int STAGE_B = (32*(96+4) + 32*(128+8))*4;    // 30208
        constexpr int SMEM = (3*STAGE_B > 96*128*4) ? 3*STAGE_B : 96*128*4;   // 90624
        cudaFuncSetAttribute(kfn, cudaFuncAttributeMaxDynamicSharedMemorySize, SMEM);
        dim3 grid(49152/96, 256/128);
        kfn<<<grid, 128, SMEM>>>(x, out, 262144);
    }
    // seg2: D=5, MUL=128. Tile 160x128x16, 4 warps of 80x64, single-buffer
    // (already at 255 regs; BK=16 has only 2 kk steps).
    {
        auto kfn = seg_linear_tc<5,160,128,16,80,64,1280,128,false>;
        constexpr int STAGE_B = (32*(16*5+4) + 16*(128+8))*4;  // 19456
        constexpr int SMEM = (3*STAGE_B > 160*128*4) ? 3*STAGE_B : 160*128*4; // 81920
        cudaFuncSetAttribute(kfn, cudaFuncAttributeMaxDynamicSharedMemorySize, SMEM);
        dim3 grid(81920/160, 128/128);
        kfn<<<grid, 128, SMEM>>>(x, out, 327680);
    }
}